// round 9
// baseline (speedup 1.0000x reference)
#include <cuda_runtime.h>
#include <cuda_bf16.h>

// Shapes (fixed): B=1, C=8, O=8, G=12, X=Y=Z=12, H=8, W=40, Bb=7 (basis), 27 taps
// x      : (1,8,12,12,12,8,40) f32   strides: c 552960, xi 46080, yi 3840, zi 320, h 40, w 1
// weight : (8,8,3,3,3,7)       f32
// bias   : (8,3,3,3)           f32
// basis  : (12,7,3,3)          f32
// out    : (1,96,12,12,12,8,40) f32
//
// Factored algorithm:
//   Y[b,o,h,w]   = sum_{c,f} x[c, n+f, h, w] * weight[o,c,f,b]          (per n)
//   out[g*8+o,.] = biasSum[o] + sum_{b,u,v} basis[(g+border)%12,b,u,v] * Y[b,o,hh0+u,ww0+v]
// NT=320, 104KB smem, 2 CTAs/SM. Grid = 592 CTAs (= exactly 2 waves at occ 2);
// CTAs bid<137 process two cells (bid, 592+bid) to kill the partial third wave.

#define NT 320
#define GRID 592
#define EXTRA 137   // 729 - 592
// smem floats: sWf[2*512] + sBp[2016] + sBiasS[16] + sX[2*2560] + sY[56*320]
#define SMEM_FLOATS (1024 + 2016 + 16 + 5120 + 17920)
#define SMEM_BYTES (SMEM_FLOATS * 4)

typedef unsigned long long ull;

__device__ __forceinline__ void fma2(ull& d, ull a, ull b) {
    asm("fma.rn.f32x2 %0, %1, %2, %0;" : "+l"(d) : "l"(a), "l"(b));
}
__device__ __forceinline__ ull pack2(float lo, float hi) {
    ull r; asm("mov.b64 %0, {%1, %2};" : "=l"(r) : "f"(lo), "f"(hi)); return r;
}
__device__ __forceinline__ void unpack2(float& lo, float& hi, ull v) {
    asm("mov.b64 {%0, %1}, %2;" : "=f"(lo), "=f"(hi) : "l"(v));
}

__device__ float gW[27 * 512];      // [f][c][o*8+b], b==7 zero-padded
__device__ float gBp[2 * 63 * 16];  // [shift][kk][g(12, pad 16)]: pre-rotated basis
__device__ float gBiasS[8];

// zero_shell + one-shot prep (first blocks also build gW/gBp/gBiasS).
__global__ __launch_bounds__(512)
void zero_prep(const float* __restrict__ weight,
               const float* __restrict__ bias,
               const float* __restrict__ basis,
               float* __restrict__ out)
{
    const int blk = blockIdx.x, tid = threadIdx.x;

    if (blk < 27) {               // 27*512 = 13824 = gW elements
        int idx = blk * 512 + tid;
        int f   = idx >> 9;
        int rem = idx & 511;
        int c   = rem >> 6;
        int col = rem & 63;
        int o = col >> 3, b = col & 7;
        gW[idx] = (b < 7) ? weight[o * 1512 + c * 189 + f * 7 + b] : 0.f;
    } else if (blk == 27) {
        if (tid < 8) {
            float s = 0.f;
            #pragma unroll
            for (int t = 0; t < 27; t++) s += bias[tid * 27 + t];
            gBiasS[tid] = s;
        }
        for (int i = tid; i < 2016; i += 512) {
            int s  = i / 1008;
            int kk = (i % 1008) >> 4;
            int g  = i & 15;
            int ge = g + s; if (ge >= 12) ge -= 12;
            gBp[i] = (g < 12) ? basis[ge * 63 + kk] : 0.f;
        }
    }

    // shell zeroing: one thread = one float4 slot; interior skipped
    const int idx   = blk * 512 + tid;
    const int cellE = idx / 80;
    const int s4    = idx % 80;
    const int go    = cellE / 1728;
    const int cell  = cellE % 1728;
    const int cx = cell / 144, cy = (cell / 12) % 12, cz = cell % 12;
    if (cx >= 1 && cx <= 9 && cy >= 1 && cy <= 9 && cz >= 1 && cz <= 9) return;
    reinterpret_cast<float4*>(out + (size_t)go * 552960 + (size_t)cell * 320)[s4] =
        make_float4(0.f, 0.f, 0.f, 0.f);
}

__global__ __launch_bounds__(NT, 2)
void gconv_main(const float* __restrict__ x, float* __restrict__ out)
{
    extern __shared__ float smem[];
    float* sWf    = smem;            // [2][8c][64]  double-buffered weight plane
    float* sBp    = sWf + 1024;      // [2][63][16]
    float* sBiasS = sBp + 2016;      // [8] (+8 pad)
    float* sX     = sBiasS + 16;     // [2][8][320]  double-buffered x plane
    float* sY     = sX + 5120;       // [56][320]    (o*7+b) x pix

    const int tid = threadIdx.x;
    const int bid = blockIdx.x;
    const int nCells = (bid < EXTRA) ? 2 : 1;

    // ---- stage small constants (once per CTA) ----
    {
        float4* b4 = reinterpret_cast<float4*>(sBp);
        const float4* gb4 = reinterpret_cast<const float4*>(gBp);
        for (int i = tid; i < 504; i += NT) b4[i] = gb4[i];
        if (tid < 8) sBiasS[tid] = gBiasS[tid];
    }

    // thread roles (cell-independent)
    const int op  = tid / 80;          // 0..3 -> o in {2op, 2op+1}
    const int t_q = tid % 80;          // px 4*t_q .. 4*t_q+3
    const int cA0 = tid / 80,         pA0 = tid % 80;
    const int cA1 = (tid + 320) / 80, pA1 = (tid + 320) % 80;
    const float4* gW4 = reinterpret_cast<const float4*>(gW);

    const int h = tid / 40, w = tid % 40;
    const int hh0 = min(max(h, 1), 6) - 1;
    const int ww0 = min(max(w, 1), 38) - 1;
    const int bshift = ((h == 0) | (h == 7) | (w == 0) | (w == 39)) ? 1 : 0;
    const float* bas = sBp + bshift * 1008;   // [63][16] pre-rotated

    for (int ci = 0; ci < nCells; ci++) {
        const int cell = (ci == 0) ? bid : GRID + bid;
        const int xi = cell / 81, yi = (cell / 9) % 9, zi = cell % 9;

        // ---- Phase 1: Y[o*7+b][pix] ----
        float acc[2][7][4];
        #pragma unroll
        for (int t = 0; t < 2; t++)
            #pragma unroll
            for (int i = 0; i < 7; i++)
                #pragma unroll
                for (int j = 0; j < 4; j++) acc[t][i][j] = 0.f;

        const float* xn = x + (size_t)xi * 46080 + (size_t)yi * 3840 + (size_t)zi * 320;

        float4 preX0, preX1, preW;
        {
            const float4* xb4 = reinterpret_cast<const float4*>(xn);
            preX0 = xb4[(size_t)cA0 * 138240 + pA0];
            preX1 = xb4[(size_t)cA1 * 138240 + pA1];
            if (tid < 128) preW = gW4[tid];
        }

        for (int f = 0; f < 27; f++) {
            const int buf = f & 1;
            reinterpret_cast<float4*>(sX + buf * 2560)[cA0 * 80 + pA0] = preX0;
            reinterpret_cast<float4*>(sX + buf * 2560)[cA1 * 80 + pA1] = preX1;
            if (tid < 128)
                reinterpret_cast<float4*>(sWf + buf * 512)[tid] = preW;
            if (f < 26) {
                const int fn = f + 1;
                const int fi = fn / 9, fj = (fn / 3) % 3, fk = fn % 3;
                const float4* xb4 = reinterpret_cast<const float4*>(
                    xn + fi * 46080 + fj * 3840 + fk * 320);
                preX0 = xb4[(size_t)cA0 * 138240 + pA0];
                preX1 = xb4[(size_t)cA1 * 138240 + pA1];
                if (tid < 128) preW = gW4[fn * 128 + tid];
            }
            __syncthreads();
            const float* xs = sX + buf * 2560;
            const float* wf = sWf + buf * 512;
            #pragma unroll
            for (int c = 0; c < 8; c++) {
                float4 xv = *reinterpret_cast<const float4*>(xs + c * 320 + t_q * 4);
                float xr[4] = {xv.x, xv.y, xv.z, xv.w};
                #pragma unroll
                for (int t = 0; t < 2; t++) {
                    const float* wp = wf + c * 64 + (op * 2 + t) * 8;
                    float4 w0 = *reinterpret_cast<const float4*>(wp);
                    float4 w1 = *reinterpret_cast<const float4*>(wp + 4);
                    float wr[7] = {w0.x, w0.y, w0.z, w0.w, w1.x, w1.y, w1.z};
                    #pragma unroll
                    for (int i = 0; i < 7; i++)
                        #pragma unroll
                        for (int j = 0; j < 4; j++)
                            acc[t][i][j] = fmaf(wr[i], xr[j], acc[t][i][j]);
                }
            }
        }
        __syncthreads();
        #pragma unroll
        for (int t = 0; t < 2; t++)
            #pragma unroll
            for (int i = 0; i < 7; i++) {
                float4 v = make_float4(acc[t][i][0], acc[t][i][1], acc[t][i][2], acc[t][i][3]);
                *reinterpret_cast<float4*>(sY + ((op * 2 + t) * 7 + i) * 320 + t_q * 4) = v;
            }
        __syncthreads();

        // ---- Phase 2: thread = pixel; two passes over o-halves, 12 g (6 pairs) x 4 o ----
        for (int pass = 0; pass < 2; pass++) {
            ull accP[6][4];
            #pragma unroll
            for (int o = 0; o < 4; o++) {
                float bs = sBiasS[pass * 4 + o];
                ull bp = pack2(bs, bs);
                #pragma unroll
                for (int k = 0; k < 6; k++) accP[k][o] = bp;
            }

            const int ybase = pass * 4 * 7 * 320;
            for (int b = 0; b < 7; b++) {
                #pragma unroll
                for (int u = 0; u < 3; u++) {
                    #pragma unroll
                    for (int v = 0; v < 3; v++) {
                        const int kk = b * 9 + u * 3 + v;
                        const int yoff = (hh0 + u) * 40 + (ww0 + v);
                        ull yd[4];
                        #pragma unroll
                        for (int o = 0; o < 4; o++) {
                            float yv = sY[ybase + (o * 7 + b) * 320 + yoff];
                            yd[o] = pack2(yv, yv);
                        }
                        const ulonglong2* bp = reinterpret_cast<const ulonglong2*>(bas + kk * 16);
                        ulonglong2 b01 = bp[0];   // g-pairs (0,1),(2,3)
                        ulonglong2 b23 = bp[1];   // (4,5),(6,7)
                        ulonglong2 b45 = bp[2];   // (8,9),(10,11)
                        #pragma unroll
                        for (int o = 0; o < 4; o++) {
                            fma2(accP[0][o], b01.x, yd[o]);
                            fma2(accP[1][o], b01.y, yd[o]);
                            fma2(accP[2][o], b23.x, yd[o]);
                            fma2(accP[3][o], b23.y, yd[o]);
                            fma2(accP[4][o], b45.x, yd[o]);
                            fma2(accP[5][o], b45.y, yd[o]);
                        }
                    }
                }
            }

            // ---- store: out[(2k+e)*8 + pass*4 + o, xi+1, yi+1, zi+1, px] ----
            float* ob = out + (size_t)(xi + 1) * 46080 + (size_t)(yi + 1) * 3840
                            + (size_t)(zi + 1) * 320 + tid + (size_t)pass * 4 * 552960;
            #pragma unroll
            for (int k = 0; k < 6; k++)
                #pragma unroll
                for (int o = 0; o < 4; o++) {
                    float lo, hi;
                    unpack2(lo, hi, accP[k][o]);
                    ob[(size_t)((2 * k) * 8 + o) * 552960]     = lo;
                    ob[(size_t)((2 * k + 1) * 8 + o) * 552960] = hi;
                }
        }
        // no extra barrier needed: next cell's first sX/sWf stores are ordered by
        // the f=0 __syncthreads, and sY is only rewritten after a barrier.
    }
}

extern "C" void kernel_launch(void* const* d_in, const int* in_sizes, int n_in,
                              void* d_out, int out_size)
{
    const float* x      = (const float*)d_in[0];
    const float* weight = (const float*)d_in[1];
    const float* bias   = (const float*)d_in[2];
    const float* basis  = (const float*)d_in[3];
    // d_in[4..7] = I, J, T, bias_basis: deterministic clip/border maps, computed inline.
    float* out = (float*)d_out;

    cudaFuncSetAttribute(gconv_main, cudaFuncAttributeMaxDynamicSharedMemorySize, SMEM_BYTES);

    zero_prep<<<25920, 512>>>(weight, bias, basis, out);
    gconv_main<<<GRID, NT, SMEM_BYTES>>>(x, out);
}

// round 10
// speedup vs baseline: 1.0451x; 1.0451x over previous
#include <cuda_runtime.h>
#include <cuda_bf16.h>

// Shapes (fixed): B=1, C=8, O=8, G=12, X=Y=Z=12, H=8, W=40, Bb=7 (basis), 27 taps
// x      : (1,8,12,12,12,8,40) f32   strides: c 552960, xi 46080, yi 3840, zi 320, h 40, w 1
// weight : (8,8,3,3,3,7)       f32
// bias   : (8,3,3,3)           f32
// basis  : (12,7,3,3)          f32
// out    : (1,96,12,12,12,8,40) f32
//
// Factored algorithm:
//   Y[b,o,h,w]   = sum_{c,f} x[c, n+f, h, w] * weight[o,c,f,b]          (per n)
//   out[g*8+o,.] = biasSum[o] + sum_{b,u,v} basis[(g+border)%12,b,u,v] * Y[b,o,hh0+u,ww0+v]
// One CTA per cell (729), NT=320, 104KB smem, 2 CTAs/SM. Scalar FFMA phase 1
// (measured: fma.rn.f32x2 is throughput-neutral on sm_103a), FFMA2 phase 2.
// Shell zeroing folded into gconv (compute-bound kernel hides the 123MB of stores).

#define NT 320
// smem floats: sWf[2*512] + sBp[2016] + sBiasS[16] + sX[2*2560] + sY[56*320]
#define SMEM_FLOATS (1024 + 2016 + 16 + 5120 + 17920)
#define SMEM_BYTES (SMEM_FLOATS * 4)

#define NSHELL 999                 // non-interior cells per channel
#define SHELL_SLOTS (96 * NSHELL * 80)   // float4 slots to zero
#define SLOT_STRIDE (729 * NT)

typedef unsigned long long ull;

__device__ __forceinline__ void fma2(ull& d, ull a, ull b) {
    asm("fma.rn.f32x2 %0, %1, %2, %0;" : "+l"(d) : "l"(a), "l"(b));
}
__device__ __forceinline__ ull pack2(float lo, float hi) {
    ull r; asm("mov.b64 %0, {%1, %2};" : "=l"(r) : "f"(lo), "f"(hi)); return r;
}
__device__ __forceinline__ void unpack2(float& lo, float& hi, ull v) {
    asm("mov.b64 {%0, %1}, %2;" : "=f"(lo), "=f"(hi) : "l"(v));
}

__device__ float gW[27 * 512];      // [f][c][o*8+b], b==7 zero-padded
__device__ float gBp[2 * 63 * 16];  // [shift][kk][g(12, pad 16)]: pre-rotated basis
__device__ float gBiasS[8];
__device__ int   gShell[NSHELL];    // shell cell indices (0..1727)

// One-shot prep: gW/gBp/gBiasS reorg + shell-cell list. 30 blocks x 512.
__global__ __launch_bounds__(512)
void prep_kernel(const float* __restrict__ weight,
                 const float* __restrict__ bias,
                 const float* __restrict__ basis)
{
    const int blk = blockIdx.x, tid = threadIdx.x;

    if (blk < 27) {               // 27*512 = 13824 = gW elements
        int idx = blk * 512 + tid;
        int f   = idx >> 9;
        int rem = idx & 511;
        int c   = rem >> 6;
        int col = rem & 63;
        int o = col >> 3, b = col & 7;
        gW[idx] = (b < 7) ? weight[o * 1512 + c * 189 + f * 7 + b] : 0.f;
    } else if (blk == 27) {
        if (tid < 8) {
            float s = 0.f;
            #pragma unroll
            for (int t = 0; t < 27; t++) s += bias[tid * 27 + t];
            gBiasS[tid] = s;
        }
        for (int i = tid; i < 2016; i += 512) {
            int s  = i / 1008;
            int kk = (i % 1008) >> 4;
            int g  = i & 15;
            int ge = g + s; if (ge >= 12) ge -= 12;
            gBp[i] = (g < 12) ? basis[ge * 63 + kk] : 0.f;
        }
    } else {
        // shell list: j-th shell cell, closed form. Interior = cx,cy,cz in [1,9].
        int j = (blk - 28) * 512 + tid;
        if (j < NSHELL) {
            int cx, cy, cz;
            if (j < 144) {                       // cx = 0 full plane
                cx = 0; cy = j / 12; cz = j % 12;
            } else if (j < 711) {                // cx = 1..9, 63 shell cells each
                int q = j - 144;
                cx = 1 + q / 63;
                int r = q % 63;
                if (r < 12)      { cy = 0;  cz = r; }
                else if (r < 39) { int t = r - 12; cy = 1 + t / 3;
                                   int m = t % 3; cz = (m == 0) ? 0 : (m == 1 ? 10 : 11); }
                else if (r < 51) { cy = 10; cz = r - 39; }
                else             { cy = 11; cz = r - 51; }
            } else {                             // cx = 10,11 full planes
                int q = j - 711;
                cx = 10 + q / 144;
                int r = q % 144;
                cy = r / 12; cz = r % 12;
            }
            gShell[j] = cx * 144 + cy * 12 + cz;
        }
    }
}

__global__ __launch_bounds__(NT, 2)
void gconv_main(const float* __restrict__ x, float* __restrict__ out)
{
    extern __shared__ float smem[];
    float* sWf    = smem;            // [2][8c][64]  double-buffered weight plane
    float* sBp    = sWf + 1024;      // [2][63][16]
    float* sBiasS = sBp + 2016;      // [8] (+8 pad)
    float* sX     = sBiasS + 16;     // [2][8][320]  double-buffered x plane
    float* sY     = sX + 5120;       // [56][320]    (o*7+b) x pix

    const int tid  = threadIdx.x;
    const int cell = blockIdx.x;
    const int xi = cell / 81, yi = (cell / 9) % 9, zi = cell % 9;

    // ---- shell zeroing (disjoint from interior writes; hidden under compute) ----
    {
        const int base = cell * NT + tid;
        const float4 z4 = make_float4(0.f, 0.f, 0.f, 0.f);
        #pragma unroll 1
        for (int k = 0; k < 33; k++) {
            int slot = base + k * SLOT_STRIDE;
            if (slot < SHELL_SLOTS) {
                int go = slot / (NSHELL * 80);
                int r  = slot % (NSHELL * 80);
                int sc = gShell[r / 80];
                int s4 = r % 80;
                reinterpret_cast<float4*>(out + (size_t)go * 552960
                                              + (size_t)sc * 320)[s4] = z4;
            }
        }
    }

    // ---- stage small constants ----
    {
        float4* b4 = reinterpret_cast<float4*>(sBp);
        const float4* gb4 = reinterpret_cast<const float4*>(gBp);
        for (int i = tid; i < 504; i += NT) b4[i] = gb4[i];
        if (tid < 8) sBiasS[tid] = gBiasS[tid];
    }

    // ---- Phase 1: Y[o*7+b][pix]; thread = (o-pair op, 4 consecutive px) ----
    const int op  = tid / 80;          // 0..3 -> o in {2op, 2op+1}
    const int t_q = tid % 80;          // px 4*t_q .. 4*t_q+3

    float acc[2][7][4];
    #pragma unroll
    for (int t = 0; t < 2; t++)
        #pragma unroll
        for (int i = 0; i < 7; i++)
            #pragma unroll
            for (int j = 0; j < 4; j++) acc[t][i][j] = 0.f;

    const float* xn = x + (size_t)xi * 46080 + (size_t)yi * 3840 + (size_t)zi * 320;
    const float4* gW4 = reinterpret_cast<const float4*>(gW);

    // staging roles: x plane = 640 float4 (2/thread); weight plane = 128 float4 (tid<128)
    const int cA0 = tid / 80,         pA0 = tid % 80;
    const int cA1 = (tid + 320) / 80, pA1 = (tid + 320) % 80;

    float4 preX0, preX1, preW;
    {
        const float4* xb4 = reinterpret_cast<const float4*>(xn);
        preX0 = xb4[(size_t)cA0 * 138240 + pA0];
        preX1 = xb4[(size_t)cA1 * 138240 + pA1];
        if (tid < 128) preW = gW4[tid];
    }

    for (int f = 0; f < 27; f++) {
        const int buf = f & 1;
        reinterpret_cast<float4*>(sX + buf * 2560)[cA0 * 80 + pA0] = preX0;
        reinterpret_cast<float4*>(sX + buf * 2560)[cA1 * 80 + pA1] = preX1;
        if (tid < 128)
            reinterpret_cast<float4*>(sWf + buf * 512)[tid] = preW;
        if (f < 26) {
            const int fn = f + 1;
            const int fi = fn / 9, fj = (fn / 3) % 3, fk = fn % 3;
            const float4* xb4 = reinterpret_cast<const float4*>(
                xn + fi * 46080 + fj * 3840 + fk * 320);
            preX0 = xb4[(size_t)cA0 * 138240 + pA0];
            preX1 = xb4[(size_t)cA1 * 138240 + pA1];
            if (tid < 128) preW = gW4[fn * 128 + tid];
        }
        __syncthreads();
        const float* xs = sX + buf * 2560;
        const float* wf = sWf + buf * 512;
        #pragma unroll
        for (int c = 0; c < 8; c++) {
            float4 xv = *reinterpret_cast<const float4*>(xs + c * 320 + t_q * 4);
            float xr[4] = {xv.x, xv.y, xv.z, xv.w};
            #pragma unroll
            for (int t = 0; t < 2; t++) {
                const float* wp = wf + c * 64 + (op * 2 + t) * 8;
                float4 w0 = *reinterpret_cast<const float4*>(wp);
                float4 w1 = *reinterpret_cast<const float4*>(wp + 4);
                float wr[7] = {w0.x, w0.y, w0.z, w0.w, w1.x, w1.y, w1.z};
                #pragma unroll
                for (int i = 0; i < 7; i++)
                    #pragma unroll
                    for (int j = 0; j < 4; j++)
                        acc[t][i][j] = fmaf(wr[i], xr[j], acc[t][i][j]);
            }
        }
    }
    __syncthreads();
    #pragma unroll
    for (int t = 0; t < 2; t++)
        #pragma unroll
        for (int i = 0; i < 7; i++) {
            float4 v = make_float4(acc[t][i][0], acc[t][i][1], acc[t][i][2], acc[t][i][3]);
            *reinterpret_cast<float4*>(sY + ((op * 2 + t) * 7 + i) * 320 + t_q * 4) = v;
        }
    __syncthreads();

    // ---- Phase 2: thread = pixel; two passes over o-halves, 12 g (6 pairs) x 4 o ----
    const int h = tid / 40, w = tid % 40;
    const int hh0 = min(max(h, 1), 6) - 1;
    const int ww0 = min(max(w, 1), 38) - 1;
    const int bshift = ((h == 0) | (h == 7) | (w == 0) | (w == 39)) ? 1 : 0;
    const float* bas = sBp + bshift * 1008;   // [63][16] pre-rotated

    for (int pass = 0; pass < 2; pass++) {
        ull accP[6][4];
        #pragma unroll
        for (int o = 0; o < 4; o++) {
            float bs = sBiasS[pass * 4 + o];
            ull bp = pack2(bs, bs);
            #pragma unroll
            for (int k = 0; k < 6; k++) accP[k][o] = bp;
        }

        const int ybase = pass * 4 * 7 * 320;
        for (int b = 0; b < 7; b++) {
            #pragma unroll
            for (int u = 0; u < 3; u++) {
                #pragma unroll
                for (int v = 0; v < 3; v++) {
                    const int kk = b * 9 + u * 3 + v;
                    const int yoff = (hh0 + u) * 40 + (ww0 + v);
                    ull yd[4];
                    #pragma unroll
                    for (int o = 0; o < 4; o++) {
                        float yv = sY[ybase + (o * 7 + b) * 320 + yoff];
                        yd[o] = pack2(yv, yv);
                    }
                    const ulonglong2* bp = reinterpret_cast<const ulonglong2*>(bas + kk * 16);
                    ulonglong2 b01 = bp[0];   // g-pairs (0,1),(2,3)
                    ulonglong2 b23 = bp[1];   // (4,5),(6,7)
                    ulonglong2 b45 = bp[2];   // (8,9),(10,11)
                    #pragma unroll
                    for (int o = 0; o < 4; o++) {
                        fma2(accP[0][o], b01.x, yd[o]);
                        fma2(accP[1][o], b01.y, yd[o]);
                        fma2(accP[2][o], b23.x, yd[o]);
                        fma2(accP[3][o], b23.y, yd[o]);
                        fma2(accP[4][o], b45.x, yd[o]);
                        fma2(accP[5][o], b45.y, yd[o]);
                    }
                }
            }
        }

        // ---- store: out[(2k+e)*8 + pass*4 + o, xi+1, yi+1, zi+1, px] ----
        float* ob = out + (size_t)(xi + 1) * 46080 + (size_t)(yi + 1) * 3840
                        + (size_t)(zi + 1) * 320 + tid + (size_t)pass * 4 * 552960;
        #pragma unroll
        for (int k = 0; k < 6; k++)
            #pragma unroll
            for (int o = 0; o < 4; o++) {
                float lo, hi;
                unpack2(lo, hi, accP[k][o]);
                ob[(size_t)((2 * k) * 8 + o) * 552960]     = lo;
                ob[(size_t)((2 * k + 1) * 8 + o) * 552960] = hi;
            }
    }
}

extern "C" void kernel_launch(void* const* d_in, const int* in_sizes, int n_in,
                              void* d_out, int out_size)
{
    const float* x      = (const float*)d_in[0];
    const float* weight = (const float*)d_in[1];
    const float* bias   = (const float*)d_in[2];
    const float* basis  = (const float*)d_in[3];
    // d_in[4..7] = I, J, T, bias_basis: deterministic clip/border maps, computed inline.
    float* out = (float*)d_out;

    cudaFuncSetAttribute(gconv_main, cudaFuncAttributeMaxDynamicSharedMemorySize, SMEM_BYTES);

    prep_kernel<<<30, 512>>>(weight, bias, basis);
    gconv_main<<<729, NT, SMEM_BYTES>>>(x, out);
}

// round 11
// speedup vs baseline: 1.2187x; 1.1661x over previous
#include <cuda_runtime.h>
#include <cuda_bf16.h>

// Shapes (fixed): B=1, C=8, O=8, G=12, X=Y=Z=12, H=8, W=40, Bb=7 (basis), 27 taps
// x      : (1,8,12,12,12,8,40) f32   strides: c 552960, xi 46080, yi 3840, zi 320, h 40, w 1
// weight : (8,8,3,3,3,7)       f32
// bias   : (8,3,3,3)           f32
// basis  : (12,7,3,3)          f32
// out    : (1,96,12,12,12,8,40) f32
//
// Factored algorithm:
//   Y[b,o,h,w]   = sum_{c,f} x[c, n+f, h, w] * weight[o,c,f,b]          (per n)
//   out[g*8+o,.] = biasSum[o] + sum_{b,u,v} basis[(g+border)%12,b,u,v] * Y[b,o,hh0+u,ww0+v]
// One CTA per cell (729), NT=320, 104KB smem, 2 CTAs/SM. Scalar FFMA phase 1
// (measured: scalar FFMA rt=2 is the wall; f32x2 is throughput-neutral), FFMA2 phase 2.
// Shell zeroing as a fire-and-forget STG epilogue (pure arithmetic indexing, no loads).

#define NT 320
// smem floats: sWf[2*512] + sBp[2016] + sBiasS[16] + sX[2*2560] + sY[56*320]
#define SMEM_FLOATS (1024 + 2016 + 16 + 5120 + 17920)
#define SMEM_BYTES (SMEM_FLOATS * 4)

#define TOT_SLOTS (96 * 1728 * 80)    // all float4 slots in out
#define NTHREADS  (729 * NT)

typedef unsigned long long ull;

__device__ __forceinline__ void fma2(ull& d, ull a, ull b) {
    asm("fma.rn.f32x2 %0, %1, %2, %0;" : "+l"(d) : "l"(a), "l"(b));
}
__device__ __forceinline__ ull pack2(float lo, float hi) {
    ull r; asm("mov.b64 %0, {%1, %2};" : "=l"(r) : "f"(lo), "f"(hi)); return r;
}
__device__ __forceinline__ void unpack2(float& lo, float& hi, ull v) {
    asm("mov.b64 {%0, %1}, %2;" : "=f"(lo), "=f"(hi) : "l"(v));
}

__device__ float gW[27 * 512];      // [f][c][o*8+b], b==7 zero-padded
__device__ float gBp[2 * 63 * 16];  // [shift][kk][g(12, pad 16)]: pre-rotated basis
__device__ float gBiasS[8];

// One-shot prep: gW/gBp/gBiasS reorganization. 28 blocks x 512.
__global__ __launch_bounds__(512)
void prep_kernel(const float* __restrict__ weight,
                 const float* __restrict__ bias,
                 const float* __restrict__ basis)
{
    const int blk = blockIdx.x, tid = threadIdx.x;

    if (blk < 27) {               // 27*512 = 13824 = gW elements
        int idx = blk * 512 + tid;
        int f   = idx >> 9;
        int rem = idx & 511;
        int c   = rem >> 6;
        int col = rem & 63;
        int o = col >> 3, b = col & 7;
        gW[idx] = (b < 7) ? weight[o * 1512 + c * 189 + f * 7 + b] : 0.f;
    } else {
        if (tid < 8) {
            float s = 0.f;
            #pragma unroll
            for (int t = 0; t < 27; t++) s += bias[tid * 27 + t];
            gBiasS[tid] = s;
        }
        for (int i = tid; i < 2016; i += 512) {
            int s  = i / 1008;
            int kk = (i % 1008) >> 4;
            int g  = i & 15;
            int ge = g + s; if (ge >= 12) ge -= 12;
            gBp[i] = (g < 12) ? basis[ge * 63 + kk] : 0.f;
        }
    }
}

__global__ __launch_bounds__(NT, 2)
void gconv_main(const float* __restrict__ x, float* __restrict__ out)
{
    extern __shared__ float smem[];
    float* sWf    = smem;            // [2][8c][64]  double-buffered weight plane
    float* sBp    = sWf + 1024;      // [2][63][16]
    float* sBiasS = sBp + 2016;      // [8] (+8 pad)
    float* sX     = sBiasS + 16;     // [2][8][320]  double-buffered x plane
    float* sY     = sX + 5120;       // [56][320]    (o*7+b) x pix

    const int tid  = threadIdx.x;
    const int cell = blockIdx.x;
    const int xi = cell / 81, yi = (cell / 9) % 9, zi = cell % 9;

    // ---- stage small constants ----
    {
        float4* b4 = reinterpret_cast<float4*>(sBp);
        const float4* gb4 = reinterpret_cast<const float4*>(gBp);
        for (int i = tid; i < 504; i += NT) b4[i] = gb4[i];
        if (tid < 8) sBiasS[tid] = gBiasS[tid];
    }

    // ---- Phase 1: Y[o*7+b][pix]; thread = (o-pair op, 4 consecutive px) ----
    const int op  = tid / 80;          // 0..3 -> o in {2op, 2op+1}
    const int t_q = tid % 80;          // px 4*t_q .. 4*t_q+3

    float acc[2][7][4];
    #pragma unroll
    for (int t = 0; t < 2; t++)
        #pragma unroll
        for (int i = 0; i < 7; i++)
            #pragma unroll
            for (int j = 0; j < 4; j++) acc[t][i][j] = 0.f;

    const float* xn = x + (size_t)xi * 46080 + (size_t)yi * 3840 + (size_t)zi * 320;
    const float4* gW4 = reinterpret_cast<const float4*>(gW);

    // staging roles: x plane = 640 float4 (2/thread); weight plane = 128 float4 (tid<128)
    const int cA0 = tid / 80,         pA0 = tid % 80;
    const int cA1 = (tid + 320) / 80, pA1 = (tid + 320) % 80;

    float4 preX0, preX1, preW;
    {
        const float4* xb4 = reinterpret_cast<const float4*>(xn);
        preX0 = xb4[(size_t)cA0 * 138240 + pA0];
        preX1 = xb4[(size_t)cA1 * 138240 + pA1];
        if (tid < 128) preW = gW4[tid];
    }

    for (int f = 0; f < 27; f++) {
        const int buf = f & 1;
        reinterpret_cast<float4*>(sX + buf * 2560)[cA0 * 80 + pA0] = preX0;
        reinterpret_cast<float4*>(sX + buf * 2560)[cA1 * 80 + pA1] = preX1;
        if (tid < 128)
            reinterpret_cast<float4*>(sWf + buf * 512)[tid] = preW;
        if (f < 26) {
            const int fn = f + 1;
            const int fi = fn / 9, fj = (fn / 3) % 3, fk = fn % 3;
            const float4* xb4 = reinterpret_cast<const float4*>(
                xn + fi * 46080 + fj * 3840 + fk * 320);
            preX0 = xb4[(size_t)cA0 * 138240 + pA0];
            preX1 = xb4[(size_t)cA1 * 138240 + pA1];
            if (tid < 128) preW = gW4[fn * 128 + tid];
        }
        __syncthreads();
        const float* xs = sX + buf * 2560;
        const float* wf = sWf + buf * 512;
        #pragma unroll
        for (int c = 0; c < 8; c++) {
            float4 xv = *reinterpret_cast<const float4*>(xs + c * 320 + t_q * 4);
            float xr[4] = {xv.x, xv.y, xv.z, xv.w};
            #pragma unroll
            for (int t = 0; t < 2; t++) {
                const float* wp = wf + c * 64 + (op * 2 + t) * 8;
                float4 w0 = *reinterpret_cast<const float4*>(wp);
                float4 w1 = *reinterpret_cast<const float4*>(wp + 4);
                float wr[7] = {w0.x, w0.y, w0.z, w0.w, w1.x, w1.y, w1.z};
                #pragma unroll
                for (int i = 0; i < 7; i++)
                    #pragma unroll
                    for (int j = 0; j < 4; j++)
                        acc[t][i][j] = fmaf(wr[i], xr[j], acc[t][i][j]);
            }
        }
    }
    __syncthreads();
    #pragma unroll
    for (int t = 0; t < 2; t++)
        #pragma unroll
        for (int i = 0; i < 7; i++) {
            float4 v = make_float4(acc[t][i][0], acc[t][i][1], acc[t][i][2], acc[t][i][3]);
            *reinterpret_cast<float4*>(sY + ((op * 2 + t) * 7 + i) * 320 + t_q * 4) = v;
        }
    __syncthreads();

    // ---- Phase 2: thread = pixel; two passes over o-halves, 12 g (6 pairs) x 4 o ----
    const int h = tid / 40, w = tid % 40;
    const int hh0 = min(max(h, 1), 6) - 1;
    const int ww0 = min(max(w, 1), 38) - 1;
    const int bshift = ((h == 0) | (h == 7) | (w == 0) | (w == 39)) ? 1 : 0;
    const float* bas = sBp + bshift * 1008;   // [63][16] pre-rotated

    for (int pass = 0; pass < 2; pass++) {
        ull accP[6][4];
        #pragma unroll
        for (int o = 0; o < 4; o++) {
            float bs = sBiasS[pass * 4 + o];
            ull bp = pack2(bs, bs);
            #pragma unroll
            for (int k = 0; k < 6; k++) accP[k][o] = bp;
        }

        const int ybase = pass * 4 * 7 * 320;
        for (int b = 0; b < 7; b++) {
            #pragma unroll
            for (int u = 0; u < 3; u++) {
                #pragma unroll
                for (int v = 0; v < 3; v++) {
                    const int kk = b * 9 + u * 3 + v;
                    const int yoff = (hh0 + u) * 40 + (ww0 + v);
                    ull yd[4];
                    #pragma unroll
                    for (int o = 0; o < 4; o++) {
                        float yv = sY[ybase + (o * 7 + b) * 320 + yoff];
                        yd[o] = pack2(yv, yv);
                    }
                    const ulonglong2* bp = reinterpret_cast<const ulonglong2*>(bas + kk * 16);
                    ulonglong2 b01 = bp[0];   // g-pairs (0,1),(2,3)
                    ulonglong2 b23 = bp[1];   // (4,5),(6,7)
                    ulonglong2 b45 = bp[2];   // (8,9),(10,11)
                    #pragma unroll
                    for (int o = 0; o < 4; o++) {
                        fma2(accP[0][o], b01.x, yd[o]);
                        fma2(accP[1][o], b01.y, yd[o]);
                        fma2(accP[2][o], b23.x, yd[o]);
                        fma2(accP[3][o], b23.y, yd[o]);
                        fma2(accP[4][o], b45.x, yd[o]);
                        fma2(accP[5][o], b45.y, yd[o]);
                    }
                }
            }
        }

        // ---- store: out[(2k+e)*8 + pass*4 + o, xi+1, yi+1, zi+1, px] ----
        float* ob = out + (size_t)(xi + 1) * 46080 + (size_t)(yi + 1) * 3840
                        + (size_t)(zi + 1) * 320 + tid + (size_t)pass * 4 * 552960;
        #pragma unroll
        for (int k = 0; k < 6; k++)
            #pragma unroll
            for (int o = 0; o < 4; o++) {
                float lo, hi;
                unpack2(lo, hi, accP[k][o]);
                ob[(size_t)((2 * k) * 8 + o) * 552960]     = lo;
                ob[(size_t)((2 * k + 1) * 8 + o) * 552960] = hi;
            }
    }

    // ---- Epilogue: shell zeroing. Fire-and-forget STG.128 with pure-arithmetic
    // indexing (no loads, no sync needed: shell addresses disjoint from interior).
    // Drains under other CTAs' compute.
    {
        const int base = cell * NT + tid;
        const float4 z4 = make_float4(0.f, 0.f, 0.f, 0.f);
        #pragma unroll 4
        for (int k = 0; k < 57; k++) {
            int slot = base + k * NTHREADS;
            if (slot < TOT_SLOTS) {
                int go   = slot / 138240;           // 1728*80
                int r    = slot - go * 138240;
                int cel  = r / 80;
                int s4   = r - cel * 80;
                int cx = cel / 144;
                int r2 = cel - cx * 144;
                int cy = r2 / 12;
                int cz = r2 - cy * 12;
                bool interior = (cx >= 1) & (cx <= 9) & (cy >= 1) & (cy <= 9)
                              & (cz >= 1) & (cz <= 9);
                if (!interior)
                    reinterpret_cast<float4*>(out + (size_t)go * 552960
                                                  + (size_t)cel * 320)[s4] = z4;
            }
        }
    }
}

extern "C" void kernel_launch(void* const* d_in, const int* in_sizes, int n_in,
                              void* d_out, int out_size)
{
    const float* x      = (const float*)d_in[0];
    const float* weight = (const float*)d_in[1];
    const float* bias   = (const float*)d_in[2];
    const float* basis  = (const float*)d_in[3];
    // d_in[4..7] = I, J, T, bias_basis: deterministic clip/border maps, computed inline.
    float* out = (float*)d_out;

    cudaFuncSetAttribute(gconv_main, cudaFuncAttributeMaxDynamicSharedMemorySize, SMEM_BYTES);

    prep_kernel<<<28, 512>>>(weight, bias, basis);
    gconv_main<<<729, NT, SMEM_BYTES>>>(x, out);
}

// round 12
// speedup vs baseline: 1.2777x; 1.0484x over previous
#include <cuda_runtime.h>
#include <cuda_bf16.h>

// Shapes (fixed): B=1, C=8, O=8, G=12, X=Y=Z=12, H=8, W=40, Bb=7 (basis), 27 taps
// x      : (1,8,12,12,12,8,40) f32   strides: c 552960, xi 46080, yi 3840, zi 320, h 40, w 1
// weight : (8,8,3,3,3,7)       f32
// bias   : (8,3,3,3)           f32
// basis  : (12,7,3,3)          f32
// out    : (1,96,12,12,12,8,40) f32
//
// Factored algorithm:
//   Y[b,o,h,w]   = sum_{c,f} x[c, n+f, h, w] * weight[o,c,f,b]          (per n)
//   out[g*8+o,.] = biasSum[o] + sum_{b,u,v} basis[(g+border)%12,b,u,v] * Y[b,o,hh0+u,ww0+v]
// One CTA per cell (729), NT=320, 104KB smem, 2 CTAs/SM. Scalar FFMA phase 1
// (measured wall), FFMA2 phase 2. Shell zeroing interleaved into the f-loop as
// fire-and-forget STG.128 with incremental carry indexing (no div, no loads).

#define NT 320
// smem floats: sWf[2*512] + sBp[2016] + sBiasS[16] + sX[2*2560] + sY[56*320]
#define SMEM_FLOATS (1024 + 2016 + 16 + 5120 + 17920)
#define SMEM_BYTES (SMEM_FLOATS * 4)

#define TOT_SLOTS (96 * 1728 * 80)    // all float4 slots in out (13,271,040)
#define NTHREADS  (729 * NT)          // 233,280 = 138240 (1 go) + 1188 cells
                                      // 1188 cells = +8 cx, +3 cy, +0 cz

typedef unsigned long long ull;

__device__ __forceinline__ void fma2(ull& d, ull a, ull b) {
    asm("fma.rn.f32x2 %0, %1, %2, %0;" : "+l"(d) : "l"(a), "l"(b));
}
__device__ __forceinline__ ull pack2(float lo, float hi) {
    ull r; asm("mov.b64 %0, {%1, %2};" : "=l"(r) : "f"(lo), "f"(hi)); return r;
}
__device__ __forceinline__ void unpack2(float& lo, float& hi, ull v) {
    asm("mov.b64 {%0, %1}, %2;" : "=f"(lo), "=f"(hi) : "l"(v));
}

__device__ float gW[27 * 512];      // [f][c][o*8+b], b==7 zero-padded
__device__ float gBp[2 * 63 * 16];  // [shift][kk][g(12, pad 16)]: pre-rotated basis
__device__ float gBiasS[8];

// One-shot prep: gW/gBp/gBiasS reorganization. 28 blocks x 512.
__global__ __launch_bounds__(512)
void prep_kernel(const float* __restrict__ weight,
                 const float* __restrict__ bias,
                 const float* __restrict__ basis)
{
    const int blk = blockIdx.x, tid = threadIdx.x;

    if (blk < 27) {               // 27*512 = 13824 = gW elements
        int idx = blk * 512 + tid;
        int f   = idx >> 9;
        int rem = idx & 511;
        int c   = rem >> 6;
        int col = rem & 63;
        int o = col >> 3, b = col & 7;
        gW[idx] = (b < 7) ? weight[o * 1512 + c * 189 + f * 7 + b] : 0.f;
    } else {
        if (tid < 8) {
            float s = 0.f;
            #pragma unroll
            for (int t = 0; t < 27; t++) s += bias[tid * 27 + t];
            gBiasS[tid] = s;
        }
        for (int i = tid; i < 2016; i += 512) {
            int s  = i / 1008;
            int kk = (i % 1008) >> 4;
            int g  = i & 15;
            int ge = g + s; if (ge >= 12) ge -= 12;
            gBp[i] = (g < 12) ? basis[ge * 63 + kk] : 0.f;
        }
    }
}

__global__ __launch_bounds__(NT, 2)
void gconv_main(const float* __restrict__ x, float* __restrict__ out)
{
    extern __shared__ float smem[];
    float* sWf    = smem;            // [2][8c][64]  double-buffered weight plane
    float* sBp    = sWf + 1024;      // [2][63][16]
    float* sBiasS = sBp + 2016;      // [8] (+8 pad)
    float* sX     = sBiasS + 16;     // [2][8][320]  double-buffered x plane
    float* sY     = sX + 5120;       // [56][320]    (o*7+b) x pix

    const int tid  = threadIdx.x;
    const int cell = blockIdx.x;
    const int xi = cell / 81, yi = (cell / 9) % 9, zi = cell % 9;

    // ---- shell-zero iterator state (address map is linear: addr = slot*16B) ----
    const int slot0 = cell * NT + tid;
    float4* zp = reinterpret_cast<float4*>(out) + slot0;
    int zcx, zcy; bool zcOut; int zkmax;
    {
        int r   = slot0 % 138240;        // within one go-channel
        int cel = r / 80;
        zcx = cel / 144;
        int r2 = cel % 144;
        zcy = r2 / 12;
        int cz = r2 % 12;
        zcOut = (cz < 1) | (cz > 9);     // per-thread constant (cz never changes)
        zkmax = (slot0 < TOT_SLOTS - 56 * NTHREADS) ? 57 : 56;
    }
    const float4 z4 = make_float4(0.f, 0.f, 0.f, 0.f);

#define SHELL_STEP()                                                        \
    {                                                                       \
        if (((unsigned)(zcx - 1) > 8u) | ((unsigned)(zcy - 1) > 8u) | zcOut)\
            *zp = z4;                                                       \
        zp += NTHREADS;                                                     \
        zcy += 3; zcx += 8;                                                 \
        if (zcy >= 12) { zcy -= 12; zcx++; }                                \
        if (zcx >= 12) zcx -= 12;                                           \
    }

    // ---- stage small constants ----
    {
        float4* b4 = reinterpret_cast<float4*>(sBp);
        const float4* gb4 = reinterpret_cast<const float4*>(gBp);
        for (int i = tid; i < 504; i += NT) b4[i] = gb4[i];
        if (tid < 8) sBiasS[tid] = gBiasS[tid];
    }

    // ---- Phase 1: Y[o*7+b][pix]; thread = (o-pair op, 4 consecutive px) ----
    const int op  = tid / 80;          // 0..3 -> o in {2op, 2op+1}
    const int t_q = tid % 80;          // px 4*t_q .. 4*t_q+3

    float acc[2][7][4];
    #pragma unroll
    for (int t = 0; t < 2; t++)
        #pragma unroll
        for (int i = 0; i < 7; i++)
            #pragma unroll
            for (int j = 0; j < 4; j++) acc[t][i][j] = 0.f;

    const float* xn = x + (size_t)xi * 46080 + (size_t)yi * 3840 + (size_t)zi * 320;
    const float4* gW4 = reinterpret_cast<const float4*>(gW);

    // staging roles: x plane = 640 float4 (2/thread); weight plane = 128 float4 (tid<128)
    const int cA0 = tid / 80,         pA0 = tid % 80;
    const int cA1 = (tid + 320) / 80, pA1 = (tid + 320) % 80;

    float4 preX0, preX1, preW;
    {
        const float4* xb4 = reinterpret_cast<const float4*>(xn);
        preX0 = xb4[(size_t)cA0 * 138240 + pA0];
        preX1 = xb4[(size_t)cA1 * 138240 + pA1];
        if (tid < 128) preW = gW4[tid];
    }

    for (int f = 0; f < 27; f++) {
        const int buf = f & 1;
        reinterpret_cast<float4*>(sX + buf * 2560)[cA0 * 80 + pA0] = preX0;
        reinterpret_cast<float4*>(sX + buf * 2560)[cA1 * 80 + pA1] = preX1;
        if (tid < 128)
            reinterpret_cast<float4*>(sWf + buf * 512)[tid] = preW;
        if (f < 26) {
            const int fn = f + 1;
            const int fi = fn / 9, fj = (fn / 3) % 3, fk = fn % 3;
            const float4* xb4 = reinterpret_cast<const float4*>(
                xn + fi * 46080 + fj * 3840 + fk * 320);
            preX0 = xb4[(size_t)cA0 * 138240 + pA0];
            preX1 = xb4[(size_t)cA1 * 138240 + pA1];
            if (tid < 128) preW = gW4[fn * 128 + tid];
        }
        __syncthreads();
        // two fire-and-forget shell zeros per f-step (54 of <=57 total; all
        // threads have zkmax >= 56 so no bound check needed here)
        SHELL_STEP();
        SHELL_STEP();
        const float* xs = sX + buf * 2560;
        const float* wf = sWf + buf * 512;
        #pragma unroll
        for (int c = 0; c < 8; c++) {
            float4 xv = *reinterpret_cast<const float4*>(xs + c * 320 + t_q * 4);
            float xr[4] = {xv.x, xv.y, xv.z, xv.w};
            #pragma unroll
            for (int t = 0; t < 2; t++) {
                const float* wp = wf + c * 64 + (op * 2 + t) * 8;
                float4 w0 = *reinterpret_cast<const float4*>(wp);
                float4 w1 = *reinterpret_cast<const float4*>(wp + 4);
                float wr[7] = {w0.x, w0.y, w0.z, w0.w, w1.x, w1.y, w1.z};
                #pragma unroll
                for (int i = 0; i < 7; i++)
                    #pragma unroll
                    for (int j = 0; j < 4; j++)
                        acc[t][i][j] = fmaf(wr[i], xr[j], acc[t][i][j]);
            }
        }
    }
    __syncthreads();
    #pragma unroll
    for (int t = 0; t < 2; t++)
        #pragma unroll
        for (int i = 0; i < 7; i++) {
            float4 v = make_float4(acc[t][i][0], acc[t][i][1], acc[t][i][2], acc[t][i][3]);
            *reinterpret_cast<float4*>(sY + ((op * 2 + t) * 7 + i) * 320 + t_q * 4) = v;
        }
    __syncthreads();

    // ---- Phase 2: thread = pixel; two passes over o-halves, 12 g (6 pairs) x 4 o ----
    const int h = tid / 40, w = tid % 40;
    const int hh0 = min(max(h, 1), 6) - 1;
    const int ww0 = min(max(w, 1), 38) - 1;
    const int bshift = ((h == 0) | (h == 7) | (w == 0) | (w == 39)) ? 1 : 0;
    const float* bas = sBp + bshift * 1008;   // [63][16] pre-rotated

    for (int pass = 0; pass < 2; pass++) {
        ull accP[6][4];
        #pragma unroll
        for (int o = 0; o < 4; o++) {
            float bs = sBiasS[pass * 4 + o];
            ull bp = pack2(bs, bs);
            #pragma unroll
            for (int k = 0; k < 6; k++) accP[k][o] = bp;
        }

        const int ybase = pass * 4 * 7 * 320;
        for (int b = 0; b < 7; b++) {
            #pragma unroll
            for (int u = 0; u < 3; u++) {
                #pragma unroll
                for (int v = 0; v < 3; v++) {
                    const int kk = b * 9 + u * 3 + v;
                    const int yoff = (hh0 + u) * 40 + (ww0 + v);
                    ull yd[4];
                    #pragma unroll
                    for (int o = 0; o < 4; o++) {
                        float yv = sY[ybase + (o * 7 + b) * 320 + yoff];
                        yd[o] = pack2(yv, yv);
                    }
                    const ulonglong2* bp = reinterpret_cast<const ulonglong2*>(bas + kk * 16);
                    ulonglong2 b01 = bp[0];   // g-pairs (0,1),(2,3)
                    ulonglong2 b23 = bp[1];   // (4,5),(6,7)
                    ulonglong2 b45 = bp[2];   // (8,9),(10,11)
                    #pragma unroll
                    for (int o = 0; o < 4; o++) {
                        fma2(accP[0][o], b01.x, yd[o]);
                        fma2(accP[1][o], b01.y, yd[o]);
                        fma2(accP[2][o], b23.x, yd[o]);
                        fma2(accP[3][o], b23.y, yd[o]);
                        fma2(accP[4][o], b45.x, yd[o]);
                        fma2(accP[5][o], b45.y, yd[o]);
                    }
                }
            }
        }

        // ---- store: out[(2k+e)*8 + pass*4 + o, xi+1, yi+1, zi+1, px] ----
        float* ob = out + (size_t)(xi + 1) * 46080 + (size_t)(yi + 1) * 3840
                        + (size_t)(zi + 1) * 320 + tid + (size_t)pass * 4 * 552960;
        #pragma unroll
        for (int k = 0; k < 6; k++)
            #pragma unroll
            for (int o = 0; o < 4; o++) {
                float lo, hi;
                unpack2(lo, hi, accP[k][o]);
                ob[(size_t)((2 * k) * 8 + o) * 552960]     = lo;
                ob[(size_t)((2 * k + 1) * 8 + o) * 552960] = hi;
            }
    }

    // ---- drain remaining shell zeros (steps 54 .. zkmax-1, at most 3) ----
    for (int k = 54; k < zkmax; k++)
        SHELL_STEP();
#undef SHELL_STEP
}

extern "C" void kernel_launch(void* const* d_in, const int* in_sizes, int n_in,
                              void* d_out, int out_size)
{
    const float* x      = (const float*)d_in[0];
    const float* weight = (const float*)d_in[1];
    const float* bias   = (const float*)d_in[2];
    const float* basis  = (const float*)d_in[3];
    // d_in[4..7] = I, J, T, bias_basis: deterministic clip/border maps, computed inline.
    float* out = (float*)d_out;

    cudaFuncSetAttribute(gconv_main, cudaFuncAttributeMaxDynamicSharedMemorySize, SMEM_BYTES);

    prep_kernel<<<28, 512>>>(weight, bias, basis);
    gconv_main<<<729, NT, SMEM_BYTES>>>(x, out);
}